// round 14
// baseline (speedup 1.0000x reference)
#include <cuda_runtime.h>
#include <cuda_bf16.h>
#include <cstdint>
#include <cstddef>

#define QL      64
#define BSZ     8
#define CACHE_L 64
#define CACHE_N 512
#define NHID    1024
#define TOPK    4

#define NPAIRS    (CACHE_N / 2)
#define ATT_ELEMS (QL * BSZ * CACHE_N)   // 262144
#define IDX_ELEMS (TOPK * QL * BSZ)      // 2048

// Q hi/lo bf16 scratch, layout [b][i][h]
__device__ __align__(16) __nv_bfloat16 g_qh[BSZ * QL * NHID];
__device__ __align__(16) __nv_bfloat16 g_ql[BSZ * QL * NHID];

// ---------------------------------------------------------------------------
__device__ __forceinline__ uint32_t smem_u32(const void* p) {
    uint32_t a;
    asm("{ .reg .u64 t; cvta.to.shared.u64 t, %1; cvt.u32.u64 %0, t; }"
        : "=r"(a) : "l"(p));
    return a;
}
__device__ __forceinline__ void cp_async16(uint32_t dst, const void* src) {
    asm volatile("cp.async.cg.shared.global [%0], [%1], 16;"
                 :: "r"(dst), "l"(src) : "memory");
}
// .noinc is load-bearing: default variant increments pending count first
// (net-zero on the barrier) and deadlocks the consumers (R13 failure).
__device__ __forceinline__ void cpasync_mbar_arrive(uint32_t addr) {
    asm volatile("cp.async.mbarrier.arrive.noinc.shared.b64 [%0];"
                 :: "r"(addr) : "memory");
}
__device__ __forceinline__ void mbar_init(uint32_t addr, uint32_t cnt) {
    asm volatile("mbarrier.init.shared.b64 [%0], %1;"
                 :: "r"(addr), "r"(cnt) : "memory");
}
__device__ __forceinline__ void mbar_arrive(uint32_t addr) {
    asm volatile("mbarrier.arrive.shared.b64 _, [%0];"
                 :: "r"(addr) : "memory");
}
__device__ __forceinline__ void mbar_wait(uint32_t addr, uint32_t parity) {
    asm volatile(
        "{\n\t.reg .pred P;\n\t"
        "W%=:\n\t"
        "mbarrier.try_wait.parity.acquire.cta.shared::cta.b64 P, [%0], %1, 0x989680;\n\t"
        "@P bra D%=;\n\t"
        "bra W%=;\n\t"
        "D%=:\n\t}"
        :: "r"(addr), "r"(parity) : "memory");
}
__device__ __forceinline__ void ldm_x4(uint32_t& r0, uint32_t& r1,
                                       uint32_t& r2, uint32_t& r3, uint32_t a) {
    asm volatile("ldmatrix.sync.aligned.m8n8.x4.shared.b16 {%0,%1,%2,%3}, [%4];"
                 : "=r"(r0), "=r"(r1), "=r"(r2), "=r"(r3) : "r"(a));
}
__device__ __forceinline__ void mma16816(float* c, const uint32_t* a,
                                         const uint32_t* b) {
    asm volatile(
        "mma.sync.aligned.m16n8k16.row.col.f32.bf16.bf16.f32 "
        "{%0,%1,%2,%3}, {%4,%5,%6,%7}, {%8,%9}, {%0,%1,%2,%3};"
        : "+f"(c[0]), "+f"(c[1]), "+f"(c[2]), "+f"(c[3])
        : "r"(a[0]), "r"(a[1]), "r"(a[2]), "r"(a[3]), "r"(b[0]), "r"(b[1]));
}

// ---------------------------------------------------------------------------
// Pass 0: split query fp32 -> (hi truncated bf16, lo round-nearest bf16)
// ---------------------------------------------------------------------------
__global__ void qprep_kernel(const float* __restrict__ query) {
    int t = blockIdx.x * 256 + threadIdx.x;     // 0..131071
    int idx = t * 4;
    float4 f = *(const float4*)(query + idx);
    int i  = idx >> 13;
    int b  = (idx >> 10) & 7;
    int hh = idx & 1023;
    int o = (b * QL + i) * NHID + hh;

    uint32_t bx = __float_as_uint(f.x), by = __float_as_uint(f.y);
    uint32_t bz = __float_as_uint(f.z), bw = __float_as_uint(f.w);
    uint2 hi;
    hi.x = __byte_perm(bx, by, 0x7632);
    hi.y = __byte_perm(bz, bw, 0x7632);
    float r0 = f.x - __uint_as_float(bx & 0xffff0000u);
    float r1 = f.y - __uint_as_float(by & 0xffff0000u);
    float r2 = f.z - __uint_as_float(bz & 0xffff0000u);
    float r3 = f.w - __uint_as_float(bw & 0xffff0000u);
    uint2 lo;
    asm("cvt.rn.bf16x2.f32 %0, %1, %2;" : "=r"(lo.x) : "f"(r1), "f"(r0));
    asm("cvt.rn.bf16x2.f32 %0, %1, %2;" : "=r"(lo.y) : "f"(r3), "f"(r2));
    *(uint2*)(g_qh + o) = hi;
    *(uint2*)(g_ql + o) = lo;
}

// ---------------------------------------------------------------------------
// Pass 1: warp-specialized split-bf16 3-term GEMM + max over tokens.
//   CTA: M=128, N=64, K=1024. 288 threads: warps 0-7 compute (16x64 tiles),
//   warp 8 = cp.async producer. A: 4-stage K=32 ring (rows padded 160B).
//   B: 2-stage K=64 ring (R5 layout). mbarrier full/empty handshake,
//   NO __syncthreads in the mainloop.
//   mbarriers live in the (never-written) 32B pads of A-ring rows 0-2,
//   keeping smem at exactly 14 x 8KB so 2 CTAs/SM co-reside.
// ---------------------------------------------------------------------------
#define A_ST    20480                   // 128 rows x 160B (128B data + 32B pad)
#define B_BASE  (4 * A_ST)              // 81920
#define B_ST    16384                   // hi 8KB + lo 8KB (64 rows x 128B)
#define SMEM_TOTAL (B_BASE + 2 * B_ST)  // 114688 = 14 * 8192
// barrier slots (8B each) inside A stage-0 row pads:
#define MBO_FULLA  128                  // row 0 pad: fullA[4]
#define MBO_EMPTYA 288                  // row 1 pad: emptyA[4]
#define MBO_FULLB  448                  // row 2 pad: fullB[2]
#define MBO_EMPTYB 464                  //            emptyB[2]

__global__ void __launch_bounds__(288, 2)
cache_gemm_kernel(const float* __restrict__ keys, float* __restrict__ out) {
    extern __shared__ char smem[];
    const uint32_t sbase = smem_u32(smem);
    const int tid  = threadIdx.x;
    const int w    = tid >> 5;
    const int lane = tid & 31;
    const int b    = blockIdx.y;
    const int n0   = blockIdx.x * 2;

    const uint32_t MB_fullA  = sbase + MBO_FULLA;
    const uint32_t MB_emptyA = sbase + MBO_EMPTYA;
    const uint32_t MB_fullB  = sbase + MBO_FULLB;
    const uint32_t MB_emptyB = sbase + MBO_EMPTYB;

    if (tid == 0) {
        #pragma unroll
        for (int s = 0; s < 4; s++) {
            mbar_init(MB_fullA  + s * 8, 32);   // producer lane completions
            mbar_init(MB_emptyA + s * 8, 256);  // consumer thread arrivals
        }
        #pragma unroll
        for (int s = 0; s < 2; s++) {
            mbar_init(MB_fullB  + s * 8, 32);
            mbar_init(MB_emptyB + s * 8, 256);
        }
    }
    __syncthreads();

    if (w == 8) {
        // =================== producer warp ===================
        const int t = lane;
        const float* arow[4];
        uint32_t adst[4];
        #pragma unroll
        for (int c = 0; c < 4; c++) {
            int r = t * 4 + c;
            arow[c] = keys
                + ((size_t)(n0 + (r >> 6)) * BSZ + b) * (CACHE_L * NHID)
                + (size_t)(r & 63) * NHID;
            adst[c] = sbase + (uint32_t)(r * 160);
        }
        #pragma unroll 1
        for (int kc = 0; kc < 32; kc++) {
            const int sA = kc & 3;
            if (kc >= 4) mbar_wait(MB_emptyA + sA * 8, ((kc >> 2) + 1) & 1);
            const uint32_t dA = (uint32_t)(sA * A_ST);
            #pragma unroll
            for (int c = 0; c < 4; c++) {
                const float* s = arow[c] + kc * 32;
                uint32_t d = adst[c] + dA;
                #pragma unroll
                for (int g = 0; g < 8; g++)
                    cp_async16(d + g * 16, s + g * 4);
            }
            cpasync_mbar_arrive(MB_fullA + sA * 8);

            if ((kc & 1) == 0) {
                const int kb = kc >> 1, sB = kb & 1;
                if (kb >= 2) mbar_wait(MB_emptyB + sB * 8, ((kb >> 1) + 1) & 1);
                const uint32_t dBb = sbase + B_BASE + sB * B_ST;
                #pragma unroll
                for (int m = 0; m < 8; m++) {
                    int tp = t + 32 * m;
                    int br = tp >> 3;
                    int bk = (tp & 7) * 16;
                    size_t so = ((size_t)b * QL + br) * NHID + (tp & 7) * 8;
                    #pragma unroll
                    for (int jj = 0; jj < 4; jj++) {
                        int half = jj >> 1;
                        int row  = br + (jj & 1) * 32;
                        const __nv_bfloat16* sp = (half ? g_ql : g_qh)
                            + so + (size_t)(jj & 1) * 32 * NHID
                            + (size_t)kb * 64;
                        uint32_t d = dBb + half * 8192
                                   + (uint32_t)(row * 128
                                                + (bk ^ ((row & 7) << 4)));
                        cp_async16(d, sp);
                    }
                }
                cpasync_mbar_arrive(MB_fullB + sB * 8);
            }
        }
    } else {
        // =================== compute warps 0-7 ===================
        const int lt    = lane >> 3;
        const int lrow  = ((lt & 2) << 2) + (lane & 7);
        const int lkoff = (lt & 1) << 3;
        const int afr   = (lane >> 2);
        const int afk   = (lane & 3) << 1;

        float acc[8][4];
        #pragma unroll
        for (int nt = 0; nt < 8; nt++)
            #pragma unroll
            for (int c = 0; c < 4; c++) acc[nt][c] = 0.0f;

        #pragma unroll 1
        for (int kc = 0; kc < 32; kc++) {
            const int sA = kc & 3;
            const uint32_t ph = (uint32_t)((kc >> 2) & 1);
            mbar_wait(MB_fullA + sA * 8, ph);
            if ((kc & 1) == 0)
                mbar_wait(MB_fullB + ((kc >> 1) & 1) * 8, ph);

            const char* baseA = smem + sA * A_ST;
            const uint32_t bufB = sbase + B_BASE + ((kc >> 1) & 1) * B_ST;

            #pragma unroll
            for (int ks2l = 0; ks2l < 2; ks2l++) {
                const int ks2 = (kc & 1) * 2 + ks2l;  // pos in B's K=64 chunk

                // ---- B fragments via ldmatrix (hi + lo), 8 n-tiles
                uint32_t bh[8][2], bl[8][2];
                #pragma unroll
                for (int np = 0; np < 4; np++) {
                    int row = 16 * np + lrow;
                    uint32_t kb = (uint32_t)((ks2 * 16 + lkoff) * 2);
                    uint32_t swo = (uint32_t)(row * 128
                                              + (kb ^ ((row & 7) << 4)));
                    ldm_x4(bh[2 * np][0], bh[2 * np][1],
                           bh[2 * np + 1][0], bh[2 * np + 1][1], bufB + swo);
                    ldm_x4(bl[2 * np][0], bl[2 * np][1],
                           bl[2 * np + 1][0], bl[2 * np + 1][1],
                           bufB + 8192 + swo);
                }

                // ---- A fragment: LDS fp32 (160B stride, conflict-free)
                uint32_t ah[4], al[4];
                {
                    const int R = w * 16 + afr;
                    const int kidx = ks2l * 16 + afk;
                    const char* pr0 = baseA + R * 160 + kidx * 4;
                    const char* pr1 = baseA + (R + 8) * 160 + kidx * 4;
                    float2 f0 = *(const float2*)(pr0);
                    float2 f1 = *(const float2*)(pr1);
                    float2 f2 = *(const float2*)(pr0 + 32);
                    float2 f3 = *(const float2*)(pr1 + 32);
                    float2 fs[4] = {f0, f1, f2, f3};
                    #pragma unroll
                    for (int j = 0; j < 4; j++) {
                        uint32_t bx = __float_as_uint(fs[j].x);
                        uint32_t by = __float_as_uint(fs[j].y);
                        ah[j] = __byte_perm(bx, by, 0x7632);
                        float rx = fs[j].x - __uint_as_float(bx & 0xffff0000u);
                        float ry = fs[j].y - __uint_as_float(by & 0xffff0000u);
                        asm("cvt.rn.bf16x2.f32 %0, %1, %2;"
                            : "=r"(al[j]) : "f"(ry), "f"(rx));
                    }
                }

                // ---- 24 HMMA: Ah*Bh + Ah*Bl + Al*Bh
                #pragma unroll
                for (int nt = 0; nt < 8; nt++) {
                    mma16816(acc[nt], ah, bh[nt]);
                    mma16816(acc[nt], ah, bl[nt]);
                    mma16816(acc[nt], al, bh[nt]);
                }
            }

            mbar_arrive(MB_emptyA + sA * 8);
            if (kc & 1)
                mbar_arrive(MB_emptyB + ((kc >> 1) & 1) * 8);
        }

        // per-warp max, then cross-warp reduce through smem
        float vmax[8][2];
        #pragma unroll
        for (int nt = 0; nt < 8; nt++) {
            float v0 = fmaxf(acc[nt][0], acc[nt][2]);
            float v1 = fmaxf(acc[nt][1], acc[nt][3]);
            #pragma unroll
            for (int o = 4; o < 32; o <<= 1) {
                v0 = fmaxf(v0, __shfl_xor_sync(0xffffffffu, v0, o));
                v1 = fmaxf(v1, __shfl_xor_sync(0xffffffffu, v1, o));
            }
            vmax[nt][0] = v0; vmax[nt][1] = v1;
        }
        __syncthreads();   // (1) pairs with producer's post-loop sync

        float* sred = (float*)(smem + B_BASE);   // B ring is dead now
        if (lane < 4) {
            #pragma unroll
            for (int nt = 0; nt < 8; nt++) {
                sred[w * 64 + 8 * nt + 2 * lane]     = vmax[nt][0];
                sred[w * 64 + 8 * nt + 2 * lane + 1] = vmax[nt][1];
            }
        }
        __syncthreads();   // (2)

        if (tid < 128) {
            int i  = tid & 63;          // query index
            int sl = tid >> 6;          // slot within pair
            float v = fmaxf(fmaxf(sred[(4 * sl + 0) * 64 + i],
                                  sred[(4 * sl + 1) * 64 + i]),
                            fmaxf(sred[(4 * sl + 2) * 64 + i],
                                  sred[(4 * sl + 3) * 64 + i]));
            out[(size_t)i * (BSZ * CACHE_N) + (size_t)b * CACHE_N + n0 + sl] = v;
        }
        return;
    }

    // producer path: match the two consumer __syncthreads
    __syncthreads();
    __syncthreads();
}

// ---------------------------------------------------------------------------
// Pass 2: softmax over N=512 (scale 1/32) in-place + top-4 indices.
// ---------------------------------------------------------------------------
__global__ void softmax_topk_kernel(float* __restrict__ out, int write_idx) {
    const int row  = blockIdx.x * 8 + (threadIdx.x >> 5);
    const int lane = threadIdx.x & 31;
    float* p = out + (size_t)row * CACHE_N;

    float v[16];
    float m = -1e30f;
    #pragma unroll
    for (int j = 0; j < 16; j++) {
        v[j] = p[lane + 32 * j] * 0.03125f;   // THETA / sqrt(NHID)
        m = fmaxf(m, v[j]);
    }
    #pragma unroll
    for (int o = 16; o > 0; o >>= 1)
        m = fmaxf(m, __shfl_xor_sync(0xffffffffu, m, o));

    float sum = 0.0f;
    #pragma unroll
    for (int j = 0; j < 16; j++) { v[j] = expf(v[j] - m); sum += v[j]; }
    #pragma unroll
    for (int o = 16; o > 0; o >>= 1)
        sum += __shfl_xor_sync(0xffffffffu, sum, o);

    float inv = 1.0f / sum;
    #pragma unroll
    for (int j = 0; j < 16; j++) {
        v[j] *= inv;
        p[lane + 32 * j] = v[j];
    }

    if (write_idx) {
        float* oidx = out + ATT_ELEMS;
        #pragma unroll 1
        for (int k = 0; k < TOPK; k++) {
            float bv = -1.0f; int bi = 0;
            #pragma unroll
            for (int j = 0; j < 16; j++) {
                int ii = lane + 32 * j;
                if (v[j] > bv) { bv = v[j]; bi = ii; }
            }
            #pragma unroll
            for (int o = 16; o > 0; o >>= 1) {
                float ov = __shfl_xor_sync(0xffffffffu, bv, o);
                int   oi = __shfl_xor_sync(0xffffffffu, bi, o);
                if (ov > bv || (ov == bv && oi < bi)) { bv = ov; bi = oi; }
            }
            if (lane == 0) oidx[k * (QL * BSZ) + row] = (float)bi;
            if ((bi & 31) == lane) v[bi >> 5] = -1.0f;
        }
    }
}

// ---------------------------------------------------------------------------
extern "C" void kernel_launch(void* const* d_in, const int* in_sizes, int n_in,
                              void* d_out, int out_size) {
    const float* a0 = (const float*)d_in[0];
    const float* a1 = (const float*)d_in[1];
    const float* query = a0;
    const float* keys  = a1;
    if (in_sizes[0] != QL * BSZ * NHID) { query = a1; keys = a0; }

    float* out = (float*)d_out;

    qprep_kernel<<<(BSZ * QL * NHID) / 1024, 256>>>(query);

    cudaFuncSetAttribute(cache_gemm_kernel,
                         cudaFuncAttributeMaxDynamicSharedMemorySize, SMEM_TOTAL);
    cache_gemm_kernel<<<dim3(NPAIRS, BSZ), 288, SMEM_TOTAL>>>(keys, out);

    int write_idx = (out_size >= ATT_ELEMS + IDX_ELEMS) ? 1 : 0;
    softmax_topk_kernel<<<QL * BSZ / 8, 256>>>(out, write_idx);
}

// round 15
// speedup vs baseline: 1.3147x; 1.3147x over previous
#include <cuda_runtime.h>
#include <cuda_bf16.h>
#include <cstdint>
#include <cstddef>

#define QL      64
#define BSZ     8
#define CACHE_L 64
#define CACHE_N 512
#define NHID    1024
#define TOPK    4

#define NPAIRS    (CACHE_N / 2)
#define ATT_ELEMS (QL * BSZ * CACHE_N)   // 262144
#define IDX_ELEMS (TOPK * QL * BSZ)      // 2048

// Q hi/lo bf16 scratch, layout [b][i][h]
__device__ __align__(16) __nv_bfloat16 g_qh[BSZ * QL * NHID];
__device__ __align__(16) __nv_bfloat16 g_ql[BSZ * QL * NHID];

// ---------------------------------------------------------------------------
__device__ __forceinline__ uint32_t smem_u32(const void* p) {
    uint32_t a;
    asm("{ .reg .u64 t; cvta.to.shared.u64 t, %1; cvt.u32.u64 %0, t; }"
        : "=r"(a) : "l"(p));
    return a;
}

__device__ __forceinline__ void cp_async16(uint32_t dst, const void* src) {
    asm volatile("cp.async.cg.shared.global [%0], [%1], 16;"
                 :: "r"(dst), "l"(src) : "memory");
}
__device__ __forceinline__ void cp_commit() {
    asm volatile("cp.async.commit_group;" ::: "memory");
}
template <int N>
__device__ __forceinline__ void cp_wait() {
    asm volatile("cp.async.wait_group %0;" :: "n"(N) : "memory");
}

__device__ __forceinline__ void ldm_x4(uint32_t& r0, uint32_t& r1,
                                       uint32_t& r2, uint32_t& r3, uint32_t a) {
    asm volatile("ldmatrix.sync.aligned.m8n8.x4.shared.b16 {%0,%1,%2,%3}, [%4];"
                 : "=r"(r0), "=r"(r1), "=r"(r2), "=r"(r3) : "r"(a));
}

__device__ __forceinline__ void mma16816(float* c, const uint32_t* a,
                                         const uint32_t* b) {
    asm volatile(
        "mma.sync.aligned.m16n8k16.row.col.f32.bf16.bf16.f32 "
        "{%0,%1,%2,%3}, {%4,%5,%6,%7}, {%8,%9}, {%0,%1,%2,%3};"
        : "+f"(c[0]), "+f"(c[1]), "+f"(c[2]), "+f"(c[3])
        : "r"(a[0]), "r"(a[1]), "r"(a[2]), "r"(a[3]), "r"(b[0]), "r"(b[1]));
}

// ---------------------------------------------------------------------------
// Pass 0: split query fp32 -> (hi truncated bf16, lo round-nearest bf16)
// 4 elements per thread, vectorized I/O.
// ---------------------------------------------------------------------------
__global__ void qprep_kernel(const float* __restrict__ query) {
    int t = blockIdx.x * 256 + threadIdx.x;     // 0..131071
    int idx = t * 4;
    float4 f = *(const float4*)(query + idx);
    int i  = idx >> 13;
    int b  = (idx >> 10) & 7;
    int hh = idx & 1023;
    int o = (b * QL + i) * NHID + hh;

    uint32_t bx = __float_as_uint(f.x), by = __float_as_uint(f.y);
    uint32_t bz = __float_as_uint(f.z), bw = __float_as_uint(f.w);
    uint2 hi;
    hi.x = __byte_perm(bx, by, 0x7632);
    hi.y = __byte_perm(bz, bw, 0x7632);
    float r0 = f.x - __uint_as_float(bx & 0xffff0000u);
    float r1 = f.y - __uint_as_float(by & 0xffff0000u);
    float r2 = f.z - __uint_as_float(bz & 0xffff0000u);
    float r3 = f.w - __uint_as_float(bw & 0xffff0000u);
    uint2 lo;
    asm("cvt.rn.bf16x2.f32 %0, %1, %2;" : "=r"(lo.x) : "f"(r1), "f"(r0));
    asm("cvt.rn.bf16x2.f32 %0, %1, %2;" : "=r"(lo.y) : "f"(r3), "f"(r2));
    *(uint2*)(g_qh + o) = hi;
    *(uint2*)(g_ql + o) = lo;
}

// ---------------------------------------------------------------------------
// Pass 1: split-bf16 3-term GEMM (measured-best configuration).
//   CTA: M=128 (2 slots x 64 tokens), N=64, K=1024 in 16 chunks of 64.
//   8 warps, warp tile 16 x 64 (A-dup=1). A cp.async fp32 -> smem (2-stage),
//   converted in-register per fragment. B bf16 hi/lo cp.async (2-stage).
// ---------------------------------------------------------------------------
#define A_STAGE 32768                  // 128 rows x 256B (64 fp32)
#define B_STAGE 16384                  // hi 8KB + lo 8KB (64 rows x 128B)
#define B_BASE  (2 * A_STAGE)          // 65536
#define SMEM_TOTAL (B_BASE + 2 * B_STAGE)   // 98304

__global__ void __launch_bounds__(256, 2)
cache_gemm_kernel(const float* __restrict__ keys, float* __restrict__ out) {
    extern __shared__ char smem[];
    const uint32_t sbase = smem_u32(smem);
    const int tid  = threadIdx.x;
    const int w    = tid >> 5;
    const int lane = tid & 31;
    const int b    = blockIdx.y;
    const int n0   = blockIdx.x * 2;

    // ---- A cp.async mapping: 8 granules of 16B per thread per chunk
    const int arow0 = tid >> 4;                   // 0..15
    const int akb   = (tid & 15) * 16;
    const float* srcA0 = keys
        + ((size_t)n0 * BSZ + b) * (CACHE_L * NHID)
        + (size_t)arow0 * NHID + (tid & 15) * 4;
    const uint32_t dstA0 = sbase + (uint32_t)(arow0 * 256
                         + (akb ^ ((arow0 & 7) << 5)));

    // ---- B cp.async mapping: 4 granules of 16B per thread per chunk
    const int bkb   = (tid & 7) * 16;
    const int brow0 = tid >> 3;                   // 0..31
    const size_t srcBoff = ((size_t)b * QL + brow0) * NHID + (tid & 7) * 8;

    // ---- ldmatrix per-lane pieces (B fragments)
    const int lt    = lane >> 3;
    const int lrow  = ((lt & 2) << 2) + (lane & 7);
    const int lkoff = (lt & 1) << 3;

    // ---- A fragment LDS pieces: warp w owns rows [16w, 16w+16)
    const int afr = (lane >> 2);
    const int afk = (lane & 3) << 1;

    float acc[8][4];
    #pragma unroll
    for (int nt = 0; nt < 8; nt++)
        #pragma unroll
        for (int c = 0; c < 4; c++) acc[nt][c] = 0.0f;

    // ---- prologue: stage chunks 0 and 1
    #pragma unroll 1
    for (int pk = 0; pk < 2; pk++) {
        uint32_t dA = dstA0 + pk * A_STAGE;
        const float* sA = srcA0 + pk * 64;
        #pragma unroll
        for (int j = 0; j < 8; j++) {
            const float* s = sA + j * 16 * NHID
                           + ((j >= 4) ? (7 * CACHE_L * NHID) : 0);
            cp_async16(dA + j * 4096, s);
        }
        uint32_t dBb = sbase + B_BASE + pk * B_STAGE;
        #pragma unroll
        for (int j = 0; j < 4; j++) {
            int half = j >> 1;
            int row  = brow0 + (j & 1) * 32;
            const __nv_bfloat16* s = (half ? g_ql : g_qh)
                + srcBoff + (size_t)(j & 1) * 32 * NHID + pk * 64;
            uint32_t d = dBb + half * 8192
                       + (uint32_t)(row * 128 + (bkb ^ ((row & 7) << 4)));
            cp_async16(d, s);
        }
        cp_commit();
    }

    #pragma unroll 1
    for (int kc = 0; kc < 16; kc++) {
        cp_wait<1>();
        __syncthreads();

        const uint32_t bufB = sbase + B_BASE + (kc & 1) * B_STAGE;

        #pragma unroll
        for (int ks2 = 0; ks2 < 4; ks2++) {
            // ---- B fragments via ldmatrix (hi + lo), 8 n-tiles
            uint32_t bh[8][2], bl[8][2];
            #pragma unroll
            for (int np = 0; np < 4; np++) {
                int row = 16 * np + lrow;
                uint32_t kb = (uint32_t)((ks2 * 16 + lkoff) * 2);
                uint32_t swo = (uint32_t)(row * 128 + (kb ^ ((row & 7) << 4)));
                ldm_x4(bh[2 * np][0], bh[2 * np][1],
                       bh[2 * np + 1][0], bh[2 * np + 1][1], bufB + swo);
                ldm_x4(bl[2 * np][0], bl[2 * np][1],
                       bl[2 * np + 1][0], bl[2 * np + 1][1],
                       bufB + 8192 + swo);
            }

            // ---- A fragment: LDS fp32 once, convert hi/lo in-register
            uint32_t ah[4], al[4];
            {
                const int R = w * 16 + afr;
                const int kidx = ks2 * 16 + afk;
                const char* base = smem + (kc & 1) * A_STAGE;
                float2 f0 = *(const float2*)(base
                    + R * 256 + ((kidx * 4) ^ ((R & 7) << 5)));
                float2 f1 = *(const float2*)(base
                    + (R + 8) * 256 + ((kidx * 4) ^ (((R + 8) & 7) << 5)));
                float2 f2 = *(const float2*)(base
                    + R * 256 + (((kidx + 8) * 4) ^ ((R & 7) << 5)));
                float2 f3 = *(const float2*)(base
                    + (R + 8) * 256 + (((kidx + 8) * 4) ^ (((R + 8) & 7) << 5)));
                float2 fs[4] = {f0, f1, f2, f3};
                #pragma unroll
                for (int j = 0; j < 4; j++) {
                    uint32_t bx = __float_as_uint(fs[j].x);
                    uint32_t by = __float_as_uint(fs[j].y);
                    ah[j] = __byte_perm(bx, by, 0x7632);
                    float rx = fs[j].x - __uint_as_float(bx & 0xffff0000u);
                    float ry = fs[j].y - __uint_as_float(by & 0xffff0000u);
                    asm("cvt.rn.bf16x2.f32 %0, %1, %2;"
                        : "=r"(al[j]) : "f"(ry), "f"(rx));
                }
            }

            // ---- 24 HMMA: Ah*Bh + Ah*Bl + Al*Bh
            #pragma unroll
            for (int nt = 0; nt < 8; nt++) {
                mma16816(acc[nt], ah, bh[nt]);
                mma16816(acc[nt], ah, bl[nt]);
                mma16816(acc[nt], al, bh[nt]);
            }
        }
        __syncthreads();

        // ---- stage chunk kc+2 into the buffer just freed
        if (kc + 2 < 16) {
            uint32_t dA = dstA0 + (kc & 1) * A_STAGE;
            const float* sA = srcA0 + (kc + 2) * 64;
            #pragma unroll
            for (int j = 0; j < 8; j++) {
                const float* s = sA + j * 16 * NHID
                               + ((j >= 4) ? (7 * CACHE_L * NHID) : 0);
                cp_async16(dA + j * 4096, s);
            }
            uint32_t dBb = sbase + B_BASE + (kc & 1) * B_STAGE;
            #pragma unroll
            for (int j = 0; j < 4; j++) {
                int half = j >> 1;
                int row  = brow0 + (j & 1) * 32;
                const __nv_bfloat16* s = (half ? g_ql : g_qh)
                    + srcBoff + (size_t)(j & 1) * 32 * NHID + (kc + 2) * 64;
                uint32_t d = dBb + half * 8192
                           + (uint32_t)(row * 128 + (bkb ^ ((row & 7) << 4)));
                cp_async16(d, s);
            }
        }
        cp_commit();   // unconditional: keeps group accounting uniform
    }

    // ---- epilogue: max over this warp's 16 token rows, per query column ----
    float vmax[8][2];
    #pragma unroll
    for (int nt = 0; nt < 8; nt++) {
        float v0 = fmaxf(acc[nt][0], acc[nt][2]);
        float v1 = fmaxf(acc[nt][1], acc[nt][3]);
        #pragma unroll
        for (int o = 4; o < 32; o <<= 1) {
            v0 = fmaxf(v0, __shfl_xor_sync(0xffffffffu, v0, o));
            v1 = fmaxf(v1, __shfl_xor_sync(0xffffffffu, v1, o));
        }
        vmax[nt][0] = v0; vmax[nt][1] = v1;
    }

    float* sred = (float*)smem;   // 8 warps x 64 cols
    if (lane < 4) {
        #pragma unroll
        for (int nt = 0; nt < 8; nt++) {
            sred[w * 64 + 8 * nt + 2 * lane]     = vmax[nt][0];
            sred[w * 64 + 8 * nt + 2 * lane + 1] = vmax[nt][1];
        }
    }
    __syncthreads();

    if (tid < 128) {
        int i  = tid & 63;          // query index
        int sl = tid >> 6;          // slot within pair (warps 0-3 / 4-7)
        float v = fmaxf(fmaxf(sred[(4 * sl + 0) * 64 + i],
                              sred[(4 * sl + 1) * 64 + i]),
                        fmaxf(sred[(4 * sl + 2) * 64 + i],
                              sred[(4 * sl + 3) * 64 + i]));
        out[(size_t)i * (BSZ * CACHE_N) + (size_t)b * CACHE_N + n0 + sl] = v;
    }
}

// ---------------------------------------------------------------------------
// Pass 2: softmax over N=512 (scale 1/32) in-place + top-4 indices.
// One warp per (ql,b) row; no __syncthreads.
// ---------------------------------------------------------------------------
__global__ void softmax_topk_kernel(float* __restrict__ out, int write_idx) {
    const int row  = blockIdx.x * 8 + (threadIdx.x >> 5);
    const int lane = threadIdx.x & 31;
    float* p = out + (size_t)row * CACHE_N;

    float v[16];
    float m = -1e30f;
    #pragma unroll
    for (int j = 0; j < 16; j++) {
        v[j] = p[lane + 32 * j] * 0.03125f;   // THETA / sqrt(NHID)
        m = fmaxf(m, v[j]);
    }
    #pragma unroll
    for (int o = 16; o > 0; o >>= 1)
        m = fmaxf(m, __shfl_xor_sync(0xffffffffu, m, o));

    float sum = 0.0f;
    #pragma unroll
    for (int j = 0; j < 16; j++) { v[j] = expf(v[j] - m); sum += v[j]; }
    #pragma unroll
    for (int o = 16; o > 0; o >>= 1)
        sum += __shfl_xor_sync(0xffffffffu, sum, o);

    float inv = 1.0f / sum;
    #pragma unroll
    for (int j = 0; j < 16; j++) {
        v[j] *= inv;
        p[lane + 32 * j] = v[j];
    }

    if (write_idx) {
        float* oidx = out + ATT_ELEMS;
        #pragma unroll 1
        for (int k = 0; k < TOPK; k++) {
            float bv = -1.0f; int bi = 0;
            #pragma unroll
            for (int j = 0; j < 16; j++) {
                int ii = lane + 32 * j;
                if (v[j] > bv) { bv = v[j]; bi = ii; }   // ascending: tie->lower
            }
            #pragma unroll
            for (int o = 16; o > 0; o >>= 1) {
                float ov = __shfl_xor_sync(0xffffffffu, bv, o);
                int   oi = __shfl_xor_sync(0xffffffffu, bi, o);
                if (ov > bv || (ov == bv && oi < bi)) { bv = ov; bi = oi; }
            }
            if (lane == 0) oidx[k * (QL * BSZ) + row] = (float)bi;
            if ((bi & 31) == lane) v[bi >> 5] = -1.0f;   // remove winner
        }
    }
}

// ---------------------------------------------------------------------------
extern "C" void kernel_launch(void* const* d_in, const int* in_sizes, int n_in,
                              void* d_out, int out_size) {
    const float* a0 = (const float*)d_in[0];
    const float* a1 = (const float*)d_in[1];
    const float* query = a0;
    const float* keys  = a1;
    if (in_sizes[0] != QL * BSZ * NHID) { query = a1; keys = a0; }

    float* out = (float*)d_out;

    qprep_kernel<<<(BSZ * QL * NHID) / 1024, 256>>>(query);

    cudaFuncSetAttribute(cache_gemm_kernel,
                         cudaFuncAttributeMaxDynamicSharedMemorySize, SMEM_TOTAL);
    cache_gemm_kernel<<<dim3(NPAIRS, BSZ), 256, SMEM_TOTAL>>>(keys, out);

    int write_idx = (out_size >= ATT_ELEMS + IDX_ELEMS) ? 1 : 0;
    softmax_topk_kernel<<<QL * BSZ / 8, 256>>>(out, write_idx);
}